// round 10
// baseline (speedup 1.0000x reference)
#include <cuda_runtime.h>
#include <cstdint>

// SeparableConv3D: x[8,3,32,256,256] fp32, depthwise K=5 cross-correlation
// along W, then H, then T, zero 'same' padding each stage.
//
// Fused, 2-rows-per-iteration software pipeline (LDG prefetch):
//   phase A: prefetch 2 x-rows into registers (item A: all threads,
//            item B: threads 0-63), commit via aligned STS.128 at iter end
//   phase B (lane=t, wg=w-quad): W-conv via 4 aligned LDS.64 (exact 8-float
//            window, no over-read) + H-conv ring (shift by 2),
//            transposed store s(t,w) -> sbufT[cur][row][w][t]
//   phase C (warps 0-3 row a, warps 4-7 row b; lane=w, tg=t-octet):
//            T-conv = 4 LDS.128 along t per 8 outputs, from PREVIOUS sbufT
//   ONE __syncthreads per 2 h-rows.

#define NN 8
#define CC 3
#define TT 32
#define HH 256
#define WW 256
#define KK 5

#define WT 32                 // w outputs per block
#define HC 32                 // h rows per block -> grid = 24*8*8 = 1536
#define NIT ((HC + 4) / 2)    // 18 iterations of 2 rows
#define XSTRIDE 44            // x slab row stride (conflict-free)
#define STR_T 36              // sbufT per-w stride along t

__global__ void __launch_bounds__(256, 4)
sepconv3d_fused(const float* __restrict__ x,
                const float* __restrict__ w1,   // along W
                const float* __restrict__ w2,   // along H
                const float* __restrict__ w3,   // along T
                float* __restrict__ out)
{
    __shared__ float xbuf[2][2][TT * XSTRIDE];     // [buf][row]
    __shared__ float sbufT[2][2][WT * STR_T];      // [buf][row][w][t]

    const int tid  = threadIdx.x;
    const int lane = tid & 31;     // phase B: = t ; phase C: = w
    const int wg   = tid >> 5;     // phase B: w-quad

    const int bid = blockIdx.x;               // 0..1535
    const int nc  = bid >> 6;                  // n*3+c
    const int rem = bid & 63;
    const int wt  = rem >> 3;                   // 0..7
    const int hcb = rem & 7;                    // 0..7
    const int c   = nc % CC;

    const int w0 = wt * WT;
    const int h0 = hcb * HC;
    const size_t HW = (size_t)HH * WW;

    const float wW0 = w1[c*KK+0], wW1 = w1[c*KK+1], wW2 = w1[c*KK+2], wW3 = w1[c*KK+3], wW4 = w1[c*KK+4];
    const float wH0 = w2[c*KK+0], wH1 = w2[c*KK+1], wH2 = w2[c*KK+2], wH3 = w2[c*KK+3], wH4 = w2[c*KK+4];
    const float wT0 = w3[c*KK+0], wT1 = w3[c*KK+1], wT2 = w3[c*KK+2], wT3 = w3[c*KK+3], wT4 = w3[c*KK+4];

    const float* xb = x   + (size_t)nc * (TT * HW);
    float*       ob = out + (size_t)nc * (TT * HW);

    // ---- slab-load geometry: item A = tid (all), item B = threads 0-63 ----
    const int trA = tid / 10,  qA = tid - trA * 10;
    const bool hasB = (tid < 64);
    const int iB  = 256 + tid;
    const int trB = iB / 10,   qB = iB - trB * 10;
    const int gwA = w0 - 4 + 4 * qA;
    const int gwB = w0 - 4 + 4 * qB;
    const bool wvA = (gwA >= 0) && (gwA < WW);
    const bool wvB = hasB && (gwB >= 0) && (gwB < WW);
    const float* gA = xb + (size_t)trA * HW + (wvA ? gwA : 0);   // + h*WW
    const float* gB = xb + (size_t)trB * HW + (wvB ? gwB : 0);

    // smem commit addresses (aligned STS.128)
    float* const xsA00 = &xbuf[0][0][trA * XSTRIDE + 4 * qA];
    float* const xsA01 = &xbuf[0][1][trA * XSTRIDE + 4 * qA];
    float* const xsA10 = &xbuf[1][0][trA * XSTRIDE + 4 * qA];
    float* const xsA11 = &xbuf[1][1][trA * XSTRIDE + 4 * qA];
    float* const xsB00 = &xbuf[0][0][trB * XSTRIDE + 4 * qB];
    float* const xsB01 = &xbuf[0][1][trB * XSTRIDE + 4 * qB];
    float* const xsB10 = &xbuf[1][0][trB * XSTRIDE + 4 * qB];
    float* const xsB11 = &xbuf[1][1][trB * XSTRIDE + 4 * qB];

    // ---- phase C geometry: lane = w; warps 0-3 row 0, warps 4-7 row 1 ----
    const int rr    = (tid >= 128) ? 1 : 0;      // which of the 2 rows
    const int tg    = wg & 3;                    // t-octet 0..3
    const int t0    = 8 * tg;
    const int cbase = lane * STR_T;
    const int q0off = cbase + max(t0 - 4, 0);    // quad t0-4..t0-1 (clamped)
    const int q1off = cbase + t0;                // quad t0..t0+3
    const int q2off = cbase + t0 + 4;            // quad t0+4..t0+7
    const int q3off = cbase + min(t0 + 8, 28);   // quad t0+8..t0+11 (clamped)
    const float mlo = (tg == 0) ? 0.f : 1.f;     // zero-pad t<0
    const float mhi = (tg == 3) ? 0.f : 1.f;     // zero-pad t>31
    // op advances 2 rows per iter; at iter ii it points at row h0 + 2ii - 6 + rr
    float* op = ob + (size_t)t0 * HW + w0 + lane
                   + (size_t)(h0 + rr) * WW - 6 * WW;

    // H-conv register ring: g1..g4 = W-conv of the last 4 input rows
    float4 g1 = {0,0,0,0}, g2 = {0,0,0,0}, g3 = {0,0,0,0}, g4 = {0,0,0,0};
    const int scolbase = 4 * wg;
    float* const sbB00 = &sbufT[0][0][scolbase * STR_T + lane];
    float* const sbB01 = &sbufT[0][1][scolbase * STR_T + lane];
    float* const sbB10 = &sbufT[1][0][scolbase * STR_T + lane];
    float* const sbB11 = &sbufT[1][1][scolbase * STR_T + lane];

    // ---- prologue: rows h0-2, h0-1 into xbuf[0][0..1] ----
    {
        float4 v0 = {0,0,0,0}, v1 = {0,0,0,0}, u0 = {0,0,0,0}, u1 = {0,0,0,0};
        if (wvA && h0 - 2 >= 0) v0 = *reinterpret_cast<const float4*>(gA + (size_t)(h0 - 2) * WW);
        if (wvA && h0 - 1 >= 0) v1 = *reinterpret_cast<const float4*>(gA + (size_t)(h0 - 1) * WW);
        *reinterpret_cast<float4*>(xsA00) = v0;
        *reinterpret_cast<float4*>(xsA01) = v1;
        if (hasB) {
            if (wvB && h0 - 2 >= 0) u0 = *reinterpret_cast<const float4*>(gB + (size_t)(h0 - 2) * WW);
            if (wvB && h0 - 1 >= 0) u1 = *reinterpret_cast<const float4*>(gB + (size_t)(h0 - 1) * WW);
            *reinterpret_cast<float4*>(xsB00) = u0;
            *reinterpret_cast<float4*>(xsB01) = u1;
        }
    }
    __syncthreads();

    #pragma unroll 2
    for (int ii = 0; ii < NIT; ++ii) {
        const int cur = ii & 1;

        // ---- 1. prefetch rows h0+2ii, h0+2ii+1 (for next iteration) ----
        float4 pa0 = {0,0,0,0}, pa1 = {0,0,0,0}, pb0 = {0,0,0,0}, pb1 = {0,0,0,0};
        {
            const bool iv = (ii + 1 < NIT);
            const int ha = h0 + 2 * ii;
            const int hb = ha + 1;
            if (iv && wvA && ha < HH) pa0 = *reinterpret_cast<const float4*>(gA + (size_t)ha * WW);
            if (iv && wvA && hb < HH) pa1 = *reinterpret_cast<const float4*>(gA + (size_t)hb * WW);
            if (iv && wvB && ha < HH) pb0 = *reinterpret_cast<const float4*>(gB + (size_t)ha * WW);
            if (iv && wvB && hb < HH) pb1 = *reinterpret_cast<const float4*>(gB + (size_t)hb * WW);
        }

        // ---- 2. phase B: W-conv both rows (4x LDS.64 each), H-conv, s -> sbufT[cur] ----
        float4 r_a, r_b;
        {
            // window x[w-2..w+5] = slab[4wg+2 .. 4wg+9], four aligned float2s
            const float* row0 = &xbuf[cur][0][lane * XSTRIDE + scolbase + 2];
            float2 a0 = *reinterpret_cast<const float2*>(row0);       // x[w-2,w-1]
            float2 a1 = *reinterpret_cast<const float2*>(row0 + 2);   // x[w  ,w+1]
            float2 a2 = *reinterpret_cast<const float2*>(row0 + 4);   // x[w+2,w+3]
            float2 a3 = *reinterpret_cast<const float2*>(row0 + 6);   // x[w+4,w+5]
            r_a.x = wW0*a0.x + wW1*a0.y + wW2*a1.x + wW3*a1.y + wW4*a2.x;
            r_a.y = wW0*a0.y + wW1*a1.x + wW2*a1.y + wW3*a2.x + wW4*a2.y;
            r_a.z = wW0*a1.x + wW1*a1.y + wW2*a2.x + wW3*a2.y + wW4*a3.x;
            r_a.w = wW0*a1.y + wW1*a2.x + wW2*a2.y + wW3*a3.x + wW4*a3.y;

            const float* row1 = &xbuf[cur][1][lane * XSTRIDE + scolbase + 2];
            float2 b0 = *reinterpret_cast<const float2*>(row1);
            float2 b1 = *reinterpret_cast<const float2*>(row1 + 2);
            float2 b2 = *reinterpret_cast<const float2*>(row1 + 4);
            float2 b3 = *reinterpret_cast<const float2*>(row1 + 6);
            r_b.x = wW0*b0.x + wW1*b0.y + wW2*b1.x + wW3*b1.y + wW4*b2.x;
            r_b.y = wW0*b0.y + wW1*b1.x + wW2*b1.y + wW3*b2.x + wW4*b2.y;
            r_b.z = wW0*b1.x + wW1*b1.y + wW2*b2.x + wW3*b2.y + wW4*b3.x;
            r_b.w = wW0*b1.y + wW1*b2.x + wW2*b2.y + wW3*b3.x + wW4*b3.y;
        }

        if (ii >= 2) {
            float* sa = cur ? sbB10 : sbB00;
            float* sb = cur ? sbB11 : sbB01;
            sa[0 * STR_T] = wH0*g1.x + wH1*g2.x + wH2*g3.x + wH3*g4.x + wH4*r_a.x;
            sa[1 * STR_T] = wH0*g1.y + wH1*g2.y + wH2*g3.y + wH3*g4.y + wH4*r_a.y;
            sa[2 * STR_T] = wH0*g1.z + wH1*g2.z + wH2*g3.z + wH3*g4.z + wH4*r_a.z;
            sa[3 * STR_T] = wH0*g1.w + wH1*g2.w + wH2*g3.w + wH3*g4.w + wH4*r_a.w;
            sb[0 * STR_T] = wH0*g2.x + wH1*g3.x + wH2*g4.x + wH3*r_a.x + wH4*r_b.x;
            sb[1 * STR_T] = wH0*g2.y + wH1*g3.y + wH2*g4.y + wH3*r_a.y + wH4*r_b.y;
            sb[2 * STR_T] = wH0*g2.z + wH1*g3.z + wH2*g4.z + wH3*r_a.z + wH4*r_b.z;
            sb[3 * STR_T] = wH0*g2.w + wH1*g3.w + wH2*g4.w + wH3*r_a.w + wH4*r_b.w;
        }
        // ring shift by 2 (rename)
        g1 = g3; g2 = g4; g3 = r_a; g4 = r_b;

        // ---- 3. phase C: T-conv from PREVIOUS sbufT; this thread's row = rr ----
        if (ii >= 3) {
            const float* sp = sbufT[cur ^ 1][rr];
            float4 q0 = *reinterpret_cast<const float4*>(sp + q0off);
            float4 q1 = *reinterpret_cast<const float4*>(sp + q1off);
            float4 q2 = *reinterpret_cast<const float4*>(sp + q2off);
            float4 q3 = *reinterpret_cast<const float4*>(sp + q3off);
            q0.z *= mlo; q0.w *= mlo;     // zero-pad t<0
            q3.x *= mhi; q3.y *= mhi;     // zero-pad t>31

            op[0]      = wT0*q0.z + wT1*q0.w + wT2*q1.x + wT3*q1.y + wT4*q1.z;
            op[1 * HW] = wT0*q0.w + wT1*q1.x + wT2*q1.y + wT3*q1.z + wT4*q1.w;
            op[2 * HW] = wT0*q1.x + wT1*q1.y + wT2*q1.z + wT3*q1.w + wT4*q2.x;
            op[3 * HW] = wT0*q1.y + wT1*q1.z + wT2*q1.w + wT3*q2.x + wT4*q2.y;
            op[4 * HW] = wT0*q1.z + wT1*q1.w + wT2*q2.x + wT3*q2.y + wT4*q2.z;
            op[5 * HW] = wT0*q1.w + wT1*q2.x + wT2*q2.y + wT3*q2.z + wT4*q2.w;
            op[6 * HW] = wT0*q2.x + wT1*q2.y + wT2*q2.z + wT3*q2.w + wT4*q3.x;
            op[7 * HW] = wT0*q2.y + wT1*q2.z + wT2*q2.w + wT3*q3.x + wT4*q3.y;
        }
        op += 2 * WW;

        // ---- 4. commit prefetched rows into xbuf[cur^1] ----
        *reinterpret_cast<float4*>(cur ? xsA00 : xsA10) = pa0;
        *reinterpret_cast<float4*>(cur ? xsA01 : xsA11) = pa1;
        if (hasB) {
            *reinterpret_cast<float4*>(cur ? xsB00 : xsB10) = pb0;
            *reinterpret_cast<float4*>(cur ? xsB01 : xsB11) = pb1;
        }

        __syncthreads();
        // barrier orders: xbuf[cur^1] STS vs next-iter LDS; sbufT[cur] writes vs
        // next-iter phase-C reads; phase-C reads of sbufT[cur^1] vs iter+1 writes.
    }

    // ---- epilogue: last 2 output rows from sbufT[(NIT-1)&1] ----
    {
        const float* sp = sbufT[(NIT - 1) & 1][rr];
        float4 q0 = *reinterpret_cast<const float4*>(sp + q0off);
        float4 q1 = *reinterpret_cast<const float4*>(sp + q1off);
        float4 q2 = *reinterpret_cast<const float4*>(sp + q2off);
        float4 q3 = *reinterpret_cast<const float4*>(sp + q3off);
        q0.z *= mlo; q0.w *= mlo;
        q3.x *= mhi; q3.y *= mhi;

        // op has advanced 2*NIT rows: points at row h0 + 30 + rr
        op[0]      = wT0*q0.z + wT1*q0.w + wT2*q1.x + wT3*q1.y + wT4*q1.z;
        op[1 * HW] = wT0*q0.w + wT1*q1.x + wT2*q1.y + wT3*q1.z + wT4*q1.w;
        op[2 * HW] = wT0*q1.x + wT1*q1.y + wT2*q1.z + wT3*q1.w + wT4*q2.x;
        op[3 * HW] = wT0*q1.y + wT1*q1.z + wT2*q1.w + wT3*q2.x + wT4*q2.y;
        op[4 * HW] = wT0*q1.z + wT1*q1.w + wT2*q2.x + wT3*q2.y + wT4*q2.z;
        op[5 * HW] = wT0*q1.w + wT1*q2.x + wT2*q2.y + wT3*q2.z + wT4*q2.w;
        op[6 * HW] = wT0*q2.x + wT1*q2.y + wT2*q2.z + wT3*q2.w + wT4*q3.x;
        op[7 * HW] = wT0*q2.y + wT1*q2.z + wT2*q2.w + wT3*q3.x + wT4*q3.y;
    }
}

extern "C" void kernel_launch(void* const* d_in, const int* in_sizes, int n_in,
                              void* d_out, int out_size)
{
    const float* x  = (const float*)d_in[0];
    const float* w1 = (const float*)d_in[1];
    const float* w2 = (const float*)d_in[2];
    const float* w3 = (const float*)d_in[3];
    float* out = (float*)d_out;

    // 24 (n*c) * 8 (w tiles) * 8 (h chunks) = 1536 blocks
    sepconv3d_fused<<<NN * CC * (WW / WT) * (HH / HC), 256>>>(x, w1, w2, w3, out);
}

// round 11
// speedup vs baseline: 1.0351x; 1.0351x over previous
#include <cuda_runtime.h>
#include <cstdint>

// SeparableConv3D: x[8,3,32,256,256] fp32, depthwise K=5 cross-correlation
// along W, then H, then T, zero 'same' padding each stage.
//
// Fused, 2-rows-per-iteration software pipeline (LDG prefetch):
//   phase A: prefetch 2 x-rows into registers, commit via aligned STS.128
//   phase B (lane=t, wg=w-quad): W-conv via 4 aligned LDS.64 + H-conv ring,
//            store s into PAIR-INTERLEAVED staging sbufP[p=w/2][t][2]
//            (2x STS.64 per row instead of 4x STS.32)
//   phase C (thread = (row, pair, t-quad)): T-conv = 4 LDS.128 (each fetches
//            2t x 2w) -> 8 outputs stored as 4x STG.64 (coalesced)
//   ONE __syncthreads per 2 h-rows.

#define NN 8
#define CC 3
#define TT 32
#define HH 256
#define WW 256
#define KK 5

#define WT 32                 // w outputs per block
#define HC 32                 // h rows per block -> grid = 24*8*8 = 1536
#define NIT ((HC + 4) / 2)    // 18 iterations of 2 rows
#define XSTRIDE 44            // x slab row stride (conflict-free)
#define PSTR 68               // sbufP per-pair stride (floats): 2*TT + 4 pad

__global__ void __launch_bounds__(256, 4)
sepconv3d_fused(const float* __restrict__ x,
                const float* __restrict__ w1,   // along W
                const float* __restrict__ w2,   // along H
                const float* __restrict__ w3,   // along T
                float* __restrict__ out)
{
    __shared__ float xbuf[2][2][TT * XSTRIDE];       // [buf][row]
    __shared__ float sbufP[2][2][(WT / 2) * PSTR];   // [buf][row][pair][t][2]

    const int tid  = threadIdx.x;
    const int lane = tid & 31;     // phase B: = t
    const int wg   = tid >> 5;     // phase B: w-quad

    const int bid = blockIdx.x;               // 0..1535
    const int nc  = bid >> 6;                  // n*3+c
    const int rem = bid & 63;
    const int wt  = rem >> 3;                   // 0..7
    const int hcb = rem & 7;                    // 0..7
    const int c   = nc % CC;

    const int w0 = wt * WT;
    const int h0 = hcb * HC;
    const size_t HW = (size_t)HH * WW;

    const float wW0 = w1[c*KK+0], wW1 = w1[c*KK+1], wW2 = w1[c*KK+2], wW3 = w1[c*KK+3], wW4 = w1[c*KK+4];
    const float wH0 = w2[c*KK+0], wH1 = w2[c*KK+1], wH2 = w2[c*KK+2], wH3 = w2[c*KK+3], wH4 = w2[c*KK+4];
    const float wT0 = w3[c*KK+0], wT1 = w3[c*KK+1], wT2 = w3[c*KK+2], wT3 = w3[c*KK+3], wT4 = w3[c*KK+4];

    const float* xb = x   + (size_t)nc * (TT * HW);
    float*       ob = out + (size_t)nc * (TT * HW);

    // ---- slab-load geometry: item A = tid (all), item B = threads 0-63 ----
    const int trA = tid / 10,  qA = tid - trA * 10;
    const bool hasB = (tid < 64);
    const int iB  = 256 + tid;
    const int trB = iB / 10,   qB = iB - trB * 10;
    const int gwA = w0 - 4 + 4 * qA;
    const int gwB = w0 - 4 + 4 * qB;
    const bool wvA = (gwA >= 0) && (gwA < WW);
    const bool wvB = hasB && (gwB >= 0) && (gwB < WW);
    const float* gA = xb + (size_t)trA * HW + (wvA ? gwA : 0);   // + h*WW
    const float* gB = xb + (size_t)trB * HW + (wvB ? gwB : 0);

    // smem commit addresses (aligned STS.128)
    float* const xsA00 = &xbuf[0][0][trA * XSTRIDE + 4 * qA];
    float* const xsA01 = &xbuf[0][1][trA * XSTRIDE + 4 * qA];
    float* const xsA10 = &xbuf[1][0][trA * XSTRIDE + 4 * qA];
    float* const xsA11 = &xbuf[1][1][trA * XSTRIDE + 4 * qA];
    float* const xsB00 = &xbuf[0][0][trB * XSTRIDE + 4 * qB];
    float* const xsB01 = &xbuf[0][1][trB * XSTRIDE + 4 * qB];
    float* const xsB10 = &xbuf[1][0][trB * XSTRIDE + 4 * qB];
    float* const xsB11 = &xbuf[1][1][trB * XSTRIDE + 4 * qB];

    // ---- phase C geometry: thread = (row rr, pair p, t-quad tq) ----
    const int rr  = tid >> 7;          // 0: threads 0-127, 1: threads 128-255
    const int idx = tid & 127;
    const int p   = idx & 15;          // w pair: w = w0 + 2p, 2p+1
    const int tq  = idx >> 4;          // 0..7
    const int t0  = 4 * tq;
    const int pbase = p * PSTR;
    const int q0off = pbase + max(2 * t0 - 4, 0);        // t0-2, t0-1  (x2 w)
    const int q1off = pbase + 2 * t0;                    // t0,   t0+1
    const int q2off = pbase + 2 * t0 + 4;                // t0+2, t0+3
    const int q3off = pbase + min(2 * t0 + 8, 2*TT - 8); // t0+4, t0+5 (clamped)
    const float mlo = (tq == 0) ? 0.f : 1.f;   // zero-pad t<0 (whole Q0)
    const float mhi = (tq == 7) ? 0.f : 1.f;   // zero-pad t>31 (whole Q3)
    // op advances 2 rows per iter; at iter ii it points at row h0 + 2ii - 6 + rr
    float* op = ob + (size_t)t0 * HW + w0 + 2 * p
                   + (size_t)(h0 + rr) * WW - 6 * WW;

    // H-conv register ring: g1..g4 = W-conv of the last 4 input rows
    float4 g1 = {0,0,0,0}, g2 = {0,0,0,0}, g3 = {0,0,0,0}, g4 = {0,0,0,0};
    const int scolbase = 4 * wg;
    // phase-B store bases: pair 2wg at +0, pair 2wg+1 at +PSTR
    float* const sbP00 = &sbufP[0][0][(2 * wg) * PSTR + 2 * lane];
    float* const sbP01 = &sbufP[0][1][(2 * wg) * PSTR + 2 * lane];
    float* const sbP10 = &sbufP[1][0][(2 * wg) * PSTR + 2 * lane];
    float* const sbP11 = &sbufP[1][1][(2 * wg) * PSTR + 2 * lane];

    // ---- prologue: rows h0-2, h0-1 into xbuf[0][0..1] ----
    {
        float4 v0 = {0,0,0,0}, v1 = {0,0,0,0}, u0 = {0,0,0,0}, u1 = {0,0,0,0};
        if (wvA && h0 - 2 >= 0) v0 = *reinterpret_cast<const float4*>(gA + (size_t)(h0 - 2) * WW);
        if (wvA && h0 - 1 >= 0) v1 = *reinterpret_cast<const float4*>(gA + (size_t)(h0 - 1) * WW);
        *reinterpret_cast<float4*>(xsA00) = v0;
        *reinterpret_cast<float4*>(xsA01) = v1;
        if (hasB) {
            if (wvB && h0 - 2 >= 0) u0 = *reinterpret_cast<const float4*>(gB + (size_t)(h0 - 2) * WW);
            if (wvB && h0 - 1 >= 0) u1 = *reinterpret_cast<const float4*>(gB + (size_t)(h0 - 1) * WW);
            *reinterpret_cast<float4*>(xsB00) = u0;
            *reinterpret_cast<float4*>(xsB01) = u1;
        }
    }
    __syncthreads();

    #pragma unroll 2
    for (int ii = 0; ii < NIT; ++ii) {
        const int cur = ii & 1;

        // ---- 1. prefetch rows h0+2ii, h0+2ii+1 (for next iteration) ----
        float4 pa0 = {0,0,0,0}, pa1 = {0,0,0,0}, pb0 = {0,0,0,0}, pb1 = {0,0,0,0};
        {
            const bool iv = (ii + 1 < NIT);
            const int ha = h0 + 2 * ii;
            const int hb = ha + 1;
            if (iv && wvA && ha < HH) pa0 = *reinterpret_cast<const float4*>(gA + (size_t)ha * WW);
            if (iv && wvA && hb < HH) pa1 = *reinterpret_cast<const float4*>(gA + (size_t)hb * WW);
            if (iv && wvB && ha < HH) pb0 = *reinterpret_cast<const float4*>(gB + (size_t)ha * WW);
            if (iv && wvB && hb < HH) pb1 = *reinterpret_cast<const float4*>(gB + (size_t)hb * WW);
        }

        // ---- 2. phase B: W-conv both rows (4x LDS.64 each), H-conv -> sbufP[cur] ----
        float4 r_a, r_b;
        {
            const float* row0 = &xbuf[cur][0][lane * XSTRIDE + scolbase + 2];
            float2 a0 = *reinterpret_cast<const float2*>(row0);       // x[w-2,w-1]
            float2 a1 = *reinterpret_cast<const float2*>(row0 + 2);   // x[w  ,w+1]
            float2 a2 = *reinterpret_cast<const float2*>(row0 + 4);   // x[w+2,w+3]
            float2 a3 = *reinterpret_cast<const float2*>(row0 + 6);   // x[w+4,w+5]
            r_a.x = wW0*a0.x + wW1*a0.y + wW2*a1.x + wW3*a1.y + wW4*a2.x;
            r_a.y = wW0*a0.y + wW1*a1.x + wW2*a1.y + wW3*a2.x + wW4*a2.y;
            r_a.z = wW0*a1.x + wW1*a1.y + wW2*a2.x + wW3*a2.y + wW4*a3.x;
            r_a.w = wW0*a1.y + wW1*a2.x + wW2*a2.y + wW3*a3.x + wW4*a3.y;

            const float* row1 = &xbuf[cur][1][lane * XSTRIDE + scolbase + 2];
            float2 b0 = *reinterpret_cast<const float2*>(row1);
            float2 b1 = *reinterpret_cast<const float2*>(row1 + 2);
            float2 b2 = *reinterpret_cast<const float2*>(row1 + 4);
            float2 b3 = *reinterpret_cast<const float2*>(row1 + 6);
            r_b.x = wW0*b0.x + wW1*b0.y + wW2*b1.x + wW3*b1.y + wW4*b2.x;
            r_b.y = wW0*b0.y + wW1*b1.x + wW2*b1.y + wW3*b2.x + wW4*b2.y;
            r_b.z = wW0*b1.x + wW1*b1.y + wW2*b2.x + wW3*b2.y + wW4*b3.x;
            r_b.w = wW0*b1.y + wW1*b2.x + wW2*b2.y + wW3*b3.x + wW4*b3.y;
        }

        if (ii >= 2) {
            float* sa = cur ? sbP10 : sbP00;   // row a
            float* sb = cur ? sbP11 : sbP01;   // row b
            // row a: s from (g1,g2,g3,g4,r_a)
            float sax = wH0*g1.x + wH1*g2.x + wH2*g3.x + wH3*g4.x + wH4*r_a.x;
            float say = wH0*g1.y + wH1*g2.y + wH2*g3.y + wH3*g4.y + wH4*r_a.y;
            float saz = wH0*g1.z + wH1*g2.z + wH2*g3.z + wH3*g4.z + wH4*r_a.z;
            float saw = wH0*g1.w + wH1*g2.w + wH2*g3.w + wH3*g4.w + wH4*r_a.w;
            *reinterpret_cast<float2*>(sa)        = make_float2(sax, say);
            *reinterpret_cast<float2*>(sa + PSTR) = make_float2(saz, saw);
            // row b: s from (g2,g3,g4,r_a,r_b)
            float sbx = wH0*g2.x + wH1*g3.x + wH2*g4.x + wH3*r_a.x + wH4*r_b.x;
            float sby = wH0*g2.y + wH1*g3.y + wH2*g4.y + wH3*r_a.y + wH4*r_b.y;
            float sbz = wH0*g2.z + wH1*g3.z + wH2*g4.z + wH3*r_a.z + wH4*r_b.z;
            float sbw = wH0*g2.w + wH1*g3.w + wH2*g4.w + wH3*r_a.w + wH4*r_b.w;
            *reinterpret_cast<float2*>(sb)        = make_float2(sbx, sby);
            *reinterpret_cast<float2*>(sb + PSTR) = make_float2(sbz, sbw);
        }
        // ring shift by 2 (rename)
        g1 = g3; g2 = g4; g3 = r_a; g4 = r_b;

        // ---- 3. phase C: T-conv from PREVIOUS sbufP; 4t x 2w per thread ----
        if (ii >= 3) {
            const float* sp = sbufP[cur ^ 1][rr];
            float4 Q0 = *reinterpret_cast<const float4*>(sp + q0off);
            float4 Q1 = *reinterpret_cast<const float4*>(sp + q1off);
            float4 Q2 = *reinterpret_cast<const float4*>(sp + q2off);
            float4 Q3 = *reinterpret_cast<const float4*>(sp + q3off);
            Q0.x *= mlo; Q0.y *= mlo; Q0.z *= mlo; Q0.w *= mlo;
            Q3.x *= mhi; Q3.y *= mhi; Q3.z *= mhi; Q3.w *= mhi;

            // f*[m] = s(t0-2+m, w*): Q layout (t, w0),(t, w1),(t+1, w0),(t+1, w1)
            float f0[8] = {Q0.x, Q0.z, Q1.x, Q1.z, Q2.x, Q2.z, Q3.x, Q3.z};
            float f1[8] = {Q0.y, Q0.w, Q1.y, Q1.w, Q2.y, Q2.w, Q3.y, Q3.w};
            #pragma unroll
            for (int k = 0; k < 4; ++k) {
                float2 o;
                o.x = wT0*f0[k] + wT1*f0[k+1] + wT2*f0[k+2] + wT3*f0[k+3] + wT4*f0[k+4];
                o.y = wT0*f1[k] + wT1*f1[k+1] + wT2*f1[k+2] + wT3*f1[k+3] + wT4*f1[k+4];
                *reinterpret_cast<float2*>(op + (size_t)k * HW) = o;
            }
        }
        op += 2 * WW;

        // ---- 4. commit prefetched rows into xbuf[cur^1] ----
        *reinterpret_cast<float4*>(cur ? xsA00 : xsA10) = pa0;
        *reinterpret_cast<float4*>(cur ? xsA01 : xsA11) = pa1;
        if (hasB) {
            *reinterpret_cast<float4*>(cur ? xsB00 : xsB10) = pb0;
            *reinterpret_cast<float4*>(cur ? xsB01 : xsB11) = pb1;
        }

        __syncthreads();
        // barrier orders: xbuf[cur^1] STS vs next-iter LDS; sbufP[cur] writes vs
        // next-iter phase-C reads; phase-C reads of sbufP[cur^1] vs iter+1 writes.
    }

    // ---- epilogue: last 2 output rows from sbufP[(NIT-1)&1] ----
    {
        const float* sp = sbufP[(NIT - 1) & 1][rr];
        float4 Q0 = *reinterpret_cast<const float4*>(sp + q0off);
        float4 Q1 = *reinterpret_cast<const float4*>(sp + q1off);
        float4 Q2 = *reinterpret_cast<const float4*>(sp + q2off);
        float4 Q3 = *reinterpret_cast<const float4*>(sp + q3off);
        Q0.x *= mlo; Q0.y *= mlo; Q0.z *= mlo; Q0.w *= mlo;
        Q3.x *= mhi; Q3.y *= mhi; Q3.z *= mhi; Q3.w *= mhi;

        float f0[8] = {Q0.x, Q0.z, Q1.x, Q1.z, Q2.x, Q2.z, Q3.x, Q3.z};
        float f1[8] = {Q0.y, Q0.w, Q1.y, Q1.w, Q2.y, Q2.w, Q3.y, Q3.w};
        // op has advanced 2*NIT rows: points at row h0 + 30 + rr
        #pragma unroll
        for (int k = 0; k < 4; ++k) {
            float2 o;
            o.x = wT0*f0[k] + wT1*f0[k+1] + wT2*f0[k+2] + wT3*f0[k+3] + wT4*f0[k+4];
            o.y = wT0*f1[k] + wT1*f1[k+1] + wT2*f1[k+2] + wT3*f1[k+3] + wT4*f1[k+4];
            *reinterpret_cast<float2*>(op + (size_t)k * HW) = o;
        }
    }
}

extern "C" void kernel_launch(void* const* d_in, const int* in_sizes, int n_in,
                              void* d_out, int out_size)
{
    const float* x  = (const float*)d_in[0];
    const float* w1 = (const float*)d_in[1];
    const float* w2 = (const float*)d_in[2];
    const float* w3 = (const float*)d_in[3];
    float* out = (float*)d_out;

    // 24 (n*c) * 8 (w tiles) * 8 (h chunks) = 1536 blocks
    sepconv3d_fused<<<NN * CC * (WW / WT) * (HH / HC), 256>>>(x, w1, w2, w3, out);
}